// round 12
// baseline (speedup 1.0000x reference)
#include <cuda_runtime.h>

// Problem constants (match reference_code)
#define NN 4096   // batch
#define DD 8192   // feature dim
#define KE 0.14426950408889634f   // log2(e) / tau, tau = 10

__device__ __forceinline__ float ex2f(float x) {
    float y;
    asm("ex2.approx.ftz.f32 %0, %1;" : "=f"(y) : "f"(x));
    return y;
}

__global__ __launch_bounds__(256, 8) void supcon_kernel(const float* __restrict__ emb,
                                                        const long long* __restrict__ labels,
                                                        float* __restrict__ out) {
    __shared__ __align__(16) unsigned char slab[NN];
    __shared__ float sAsum[8], sAB[8], sBsum[8], sBB[8];
    __shared__ int   sAc[8], sBc[8];
    __shared__ float s_term[2];

    const int tid  = threadIdx.x;
    const int lane = tid & 31;
    const int wid  = tid >> 5;

    // Two rows handled by this block
    const int iA = blockIdx.x * 2;
    const int iB = iA + 1;

    // Build 4096-entry uint8 label table from int64 input (R4 verbatim)
    const longlong2* __restrict__ L2v = (const longlong2*)labels;
    #pragma unroll
    for (int k = 0; k < 8; k++) {
        const int idx = tid + k * 256;
        const longlong2 v = L2v[idx];
        slab[2 * idx + 0] = (unsigned char)v.x;
        slab[2 * idx + 1] = (unsigned char)v.y;
    }
    __syncthreads();   // same position as the proven R4 kernel

    const unsigned char lA = slab[iA];
    const unsigned char lB = slab[iB];
    const float4* __restrict__ rowA = (const float4*)(emb + (size_t)iA * DD);
    const float4* __restrict__ rowB = (const float4*)(emb + (size_t)iB * DD);

    // ===== Phase 1: pure streaming denominators (mask logic removed) =====
    float sumA = 0.0f, sumB = 0.0f;
    #pragma unroll
    for (int it = 0; it < 8; it++) {
        const int v4 = it * 256 + tid;
        const float4 va = rowA[v4];
        const float4 vb = rowB[v4];
        sumA += (ex2f(va.x * va.x * KE) + ex2f(va.y * va.y * KE)) +
                (ex2f(va.z * va.z * KE) + ex2f(va.w * va.w * KE));
        sumB += (ex2f(vb.x * vb.x * KE) + ex2f(vb.y * vb.y * KE)) +
                (ex2f(vb.z * vb.z * KE) + ex2f(vb.w * vb.w * KE));
    }

    // ===== Phase 2: sparse numerator (~41 matches/row, L2-warm loads) =====
    const float* __restrict__ rA = emb + (size_t)iA * DD;
    const float* __restrict__ rB = emb + (size_t)iB * DD;

    float bA = 0.0f, bB = 0.0f;
    int   cA = 0, cB = 0;
    #pragma unroll
    for (int k = 0; k < 4; k++) {
        const int q  = k * 256 + tid;      // uchar4 index in [0, 1024)
        const int j0 = q * 4;
        const uchar4 lb = ((const uchar4*)slab)[q];
        if (lb.x == lA && j0 + 0 != iA) { const float x = rA[j0 + 0]; bA += ex2f(ex2f(x * x * KE) * KE); cA++; }
        if (lb.y == lA && j0 + 1 != iA) { const float x = rA[j0 + 1]; bA += ex2f(ex2f(x * x * KE) * KE); cA++; }
        if (lb.z == lA && j0 + 2 != iA) { const float x = rA[j0 + 2]; bA += ex2f(ex2f(x * x * KE) * KE); cA++; }
        if (lb.w == lA && j0 + 3 != iA) { const float x = rA[j0 + 3]; bA += ex2f(ex2f(x * x * KE) * KE); cA++; }
        if (lb.x == lB && j0 + 0 != iB) { const float x = rB[j0 + 0]; bB += ex2f(ex2f(x * x * KE) * KE); cB++; }
        if (lb.y == lB && j0 + 1 != iB) { const float x = rB[j0 + 1]; bB += ex2f(ex2f(x * x * KE) * KE); cB++; }
        if (lb.z == lB && j0 + 2 != iB) { const float x = rB[j0 + 2]; bB += ex2f(ex2f(x * x * KE) * KE); cB++; }
        if (lb.w == lB && j0 + 3 != iB) { const float x = rB[j0 + 3]; bB += ex2f(ex2f(x * x * KE) * KE); cB++; }
    }

    // ---- intra-block reduce (R4 verbatim) ----
    #pragma unroll
    for (int o = 16; o > 0; o >>= 1) {
        sumA += __shfl_down_sync(0xFFFFFFFFu, sumA, o);
        bA   += __shfl_down_sync(0xFFFFFFFFu, bA, o);
        cA   += __shfl_down_sync(0xFFFFFFFFu, cA, o);
        sumB += __shfl_down_sync(0xFFFFFFFFu, sumB, o);
        bB   += __shfl_down_sync(0xFFFFFFFFu, bB, o);
        cB   += __shfl_down_sync(0xFFFFFFFFu, cB, o);
    }
    if (lane == 0) {
        sAsum[wid] = sumA; sAB[wid] = bA; sAc[wid] = cA;
        sBsum[wid] = sumB; sBB[wid] = bB; sBc[wid] = cB;
    }
    __syncthreads();

    if (tid == 0) {
        float ts = 0.0f, tb = 0.0f;
        int   tc = 0;
        #pragma unroll
        for (int w = 0; w < 8; w++) { ts += sAsum[w]; tb += sAB[w]; tc += sAc[w]; }
        const float xd = emb[(size_t)iA * DD + iA];
        const float dn = ts - ex2f(xd * xd * KE);
        s_term[0] = __logf(tb / (dn * (float)tc));
    }
    if (tid == 32) {
        float ts = 0.0f, tb = 0.0f;
        int   tc = 0;
        #pragma unroll
        for (int w = 0; w < 8; w++) { ts += sBsum[w]; tb += sBB[w]; tc += sBc[w]; }
        const float xd = emb[(size_t)iB * DD + iB];
        const float dn = ts - ex2f(xd * xd * KE);
        s_term[1] = __logf(tb / (dn * (float)tc));
    }
    __syncthreads();

    if (tid == 0) atomicAdd(out, s_term[0] + s_term[1]);
}

extern "C" void kernel_launch(void* const* d_in, const int* in_sizes, int n_in,
                              void* d_out, int out_size) {
    const float*     emb    = (const float*)d_in[0];
    const long long* labels = (const long long*)d_in[1];
    float*           out    = (float*)d_out;

    cudaMemsetAsync(out, 0, sizeof(float));
    supcon_kernel<<<NN / 2, 256>>>(emb, labels, out);
}

// round 13
// speedup vs baseline: 1.4087x; 1.4087x over previous
#include <cuda_runtime.h>

// Problem constants (match reference_code)
#define NN 4096   // batch
#define DD 8192   // feature dim
#define KE 0.14426950408889634f   // log2(e) / tau, tau = 10

__device__ __forceinline__ float ex2f(float x) {
    float y;
    asm("ex2.approx.ftz.f32 %0, %1;" : "=f"(y) : "f"(x));
    return y;
}

// Grid 1024 @ 7 CTAs/SM -> entire grid resident, single wave, no ragged tail.
// Each block: 2 sequential pair-passes (R4 body verbatim inside the loop).
__global__ __launch_bounds__(256, 7) void supcon_kernel(const float* __restrict__ emb,
                                                        const long long* __restrict__ labels,
                                                        float* __restrict__ out) {
    __shared__ __align__(16) unsigned char slab[NN];
    __shared__ float sAsum[8], sAB[8], sBsum[8], sBB[8];
    __shared__ int   sAc[8], sBc[8];
    __shared__ float s_term[2];

    const int tid  = threadIdx.x;
    const int lane = tid & 31;
    const int wid  = tid >> 5;

    // Build 4096-entry uint8 label table from int64 input (once per block)
    const longlong2* __restrict__ L2v = (const longlong2*)labels;
    #pragma unroll
    for (int k = 0; k < 8; k++) {
        const int idx = tid + k * 256;
        const longlong2 v = L2v[idx];
        slab[2 * idx + 0] = (unsigned char)v.x;
        slab[2 * idx + 1] = (unsigned char)v.y;
    }
    __syncthreads();

    float termAcc = 0.0f;   // meaningful on tid 0 only

    #pragma unroll 1
    for (int p = 0; p < 2; p++) {
        const int pair = p * 1024 + blockIdx.x;
        const int iA = pair * 2;
        const int iB = iA + 1;

        const unsigned char lA = slab[iA];
        const unsigned char lB = slab[iB];
        const float4* __restrict__ rowA = (const float4*)(emb + (size_t)iA * DD);
        const float4* __restrict__ rowB = (const float4*)(emb + (size_t)iB * DD);

        float sumA = 0.0f, sumB = 0.0f;   // denominators (row sums of A)
        float bA = 0.0f, bB = 0.0f;       // masked numerator sums
        int   cA = 0, cB = 0;             // masked counts

        // ---- first half: d in [0, NN): A + masked B, both rows interleaved ----
        #pragma unroll
        for (int it = 0; it < 4; it++) {
            const int v4 = it * 256 + tid;
            const int d0 = v4 * 4;
            const float4 va = rowA[v4];
            const float4 vb = rowB[v4];
            const uchar4 lb = ((const uchar4*)slab)[v4];

            float a0 = ex2f(va.x * va.x * KE);
            float a1 = ex2f(va.y * va.y * KE);
            float a2 = ex2f(va.z * va.z * KE);
            float a3 = ex2f(va.w * va.w * KE);
            sumA += (a0 + a1) + (a2 + a3);

            float b0 = ex2f(vb.x * vb.x * KE);
            float b1 = ex2f(vb.y * vb.y * KE);
            float b2 = ex2f(vb.z * vb.z * KE);
            float b3 = ex2f(vb.w * vb.w * KE);
            sumB += (b0 + b1) + (b2 + b3);

            if (lb.x == lA && d0 + 0 != iA) { bA += ex2f(a0 * KE); cA++; }
            if (lb.y == lA && d0 + 1 != iA) { bA += ex2f(a1 * KE); cA++; }
            if (lb.z == lA && d0 + 2 != iA) { bA += ex2f(a2 * KE); cA++; }
            if (lb.w == lA && d0 + 3 != iA) { bA += ex2f(a3 * KE); cA++; }

            if (lb.x == lB && d0 + 0 != iB) { bB += ex2f(b0 * KE); cB++; }
            if (lb.y == lB && d0 + 1 != iB) { bB += ex2f(b1 * KE); cB++; }
            if (lb.z == lB && d0 + 2 != iB) { bB += ex2f(b2 * KE); cB++; }
            if (lb.w == lB && d0 + 3 != iB) { bB += ex2f(b3 * KE); cB++; }
        }

        // ---- second half: d in [NN, DD): A only, both rows interleaved ----
        #pragma unroll
        for (int it = 0; it < 4; it++) {
            const int v4 = 1024 + it * 256 + tid;
            const float4 va = rowA[v4];
            const float4 vb = rowB[v4];
            sumA += (ex2f(va.x * va.x * KE) + ex2f(va.y * va.y * KE)) +
                    (ex2f(va.z * va.z * KE) + ex2f(va.w * va.w * KE));
            sumB += (ex2f(vb.x * vb.x * KE) + ex2f(vb.y * vb.y * KE)) +
                    (ex2f(vb.z * vb.z * KE) + ex2f(vb.w * vb.w * KE));
        }

        // ---- intra-block reduce ----
        #pragma unroll
        for (int o = 16; o > 0; o >>= 1) {
            sumA += __shfl_down_sync(0xFFFFFFFFu, sumA, o);
            bA   += __shfl_down_sync(0xFFFFFFFFu, bA, o);
            cA   += __shfl_down_sync(0xFFFFFFFFu, cA, o);
            sumB += __shfl_down_sync(0xFFFFFFFFu, sumB, o);
            bB   += __shfl_down_sync(0xFFFFFFFFu, bB, o);
            cB   += __shfl_down_sync(0xFFFFFFFFu, cB, o);
        }
        if (lane == 0) {
            sAsum[wid] = sumA; sAB[wid] = bA; sAc[wid] = cA;
            sBsum[wid] = sumB; sBB[wid] = bB; sBc[wid] = cB;
        }
        __syncthreads();

        if (tid == 0) {
            float ts = 0.0f, tb = 0.0f;
            int   tc = 0;
            #pragma unroll
            for (int w = 0; w < 8; w++) { ts += sAsum[w]; tb += sAB[w]; tc += sAc[w]; }
            const float xd = emb[(size_t)iA * DD + iA];
            const float dn = ts - ex2f(xd * xd * KE);
            s_term[0] = __logf(tb / (dn * (float)tc));
        }
        if (tid == 32) {
            float ts = 0.0f, tb = 0.0f;
            int   tc = 0;
            #pragma unroll
            for (int w = 0; w < 8; w++) { ts += sBsum[w]; tb += sBB[w]; tc += sBc[w]; }
            const float xd = emb[(size_t)iB * DD + iB];
            const float dn = ts - ex2f(xd * xd * KE);
            s_term[1] = __logf(tb / (dn * (float)tc));
        }
        __syncthreads();

        if (tid == 0) termAcc += s_term[0] + s_term[1];
        // next pair's smem writes are safe: every thread must pass the barrier
        // above before any pair-(p+1) shared write, and tid0 reads happen
        // before tid0 reaches that barrier's successor writes.
    }

    if (tid == 0) atomicAdd(out, termAcc);
}

extern "C" void kernel_launch(void* const* d_in, const int* in_sizes, int n_in,
                              void* d_out, int out_size) {
    const float*     emb    = (const float*)d_in[0];
    const long long* labels = (const long long*)d_in[1];
    float*           out    = (float*)d_out;

    cudaMemsetAsync(out, 0, sizeof(float));
    supcon_kernel<<<NN / 4, 256>>>(emb, labels, out);
}

// round 14
// speedup vs baseline: 1.4118x; 1.0022x over previous
#include <cuda_runtime.h>

// Problem constants (match reference_code)
#define NN 4096   // batch
#define DD 8192   // feature dim
#define KE 0.14426950408889634f   // log2(e) / tau, tau = 10

__device__ __forceinline__ float ex2f(float x) {
    float y;
    asm("ex2.approx.ftz.f32 %0, %1;" : "=f"(y) : "f"(x));
    return y;
}

// Packed helper: ex2((x*x)*KE) for 2 lanes using f32x2 packed multiplies.
__device__ __forceinline__ float2 a2f(float x0, float x1, unsigned long long ke2) {
    unsigned long long p;
    asm("mov.b64 %0, {%1, %2};" : "=l"(p) : "f"(x0), "f"(x1));
    asm("mul.rn.f32x2 %0, %0, %0;" : "+l"(p));
    asm("mul.rn.f32x2 %0, %0, %1;" : "+l"(p) : "l"(ke2));
    float2 r;
    asm("mov.b64 {%0, %1}, %2;" : "=f"(r.x), "=f"(r.y) : "l"(p));
    r.x = ex2f(r.x);
    r.y = ex2f(r.y);
    return r;
}

// Packed accumulate: a += b (f32x2)
__device__ __forceinline__ void add2(float2& a, float2 b) {
    unsigned long long pa, pb;
    asm("mov.b64 %0, {%1, %2};" : "=l"(pa) : "f"(a.x), "f"(a.y));
    asm("mov.b64 %0, {%1, %2};" : "=l"(pb) : "f"(b.x), "f"(b.y));
    asm("add.rn.f32x2 %0, %0, %1;" : "+l"(pa) : "l"(pb));
    asm("mov.b64 {%0, %1}, %2;" : "=f"(a.x), "=f"(a.y) : "l"(pa));
}

__global__ __launch_bounds__(256, 8) void supcon_kernel(const float* __restrict__ emb,
                                                        const long long* __restrict__ labels,
                                                        float* __restrict__ out) {
    __shared__ __align__(16) unsigned char slab[NN];
    __shared__ float sAsum[8], sAB[8], sBsum[8], sBB[8];
    __shared__ int   sAc[8], sBc[8];
    __shared__ float s_term[2];

    const int tid  = threadIdx.x;
    const int lane = tid & 31;
    const int wid  = tid >> 5;

    const int iA = blockIdx.x * 2;
    const int iB = iA + 1;

    // Packed KE constant (compiler-foldable)
    const unsigned int keu = __float_as_uint(KE);
    const unsigned long long ke2 = (unsigned long long)keu | ((unsigned long long)keu << 32);

    // Build 4096-entry uint8 label table from int64 input (R4 verbatim)
    const longlong2* __restrict__ L2v = (const longlong2*)labels;
    #pragma unroll
    for (int k = 0; k < 8; k++) {
        const int idx = tid + k * 256;
        const longlong2 v = L2v[idx];
        slab[2 * idx + 0] = (unsigned char)v.x;
        slab[2 * idx + 1] = (unsigned char)v.y;
    }
    __syncthreads();

    const unsigned char lA = slab[iA];
    const unsigned char lB = slab[iB];
    const float4* __restrict__ rowA = (const float4*)(emb + (size_t)iA * DD);
    const float4* __restrict__ rowB = (const float4*)(emb + (size_t)iB * DD);

    float2 sumA2 = make_float2(0.0f, 0.0f);
    float2 sumB2 = make_float2(0.0f, 0.0f);
    float bA = 0.0f, bB = 0.0f;   // masked numerator sums (diagonal included; fixed at finalize)
    int   cA = 0, cB = 0;         // masked counts (diagonal included; fixed at finalize)

    // ---- first half: d in [0, NN): A + masked B, both rows interleaved ----
    // NOTE: no j != i check — the diagonal always label-matches its own row and
    // is subtracted once at finalize.
    #pragma unroll
    for (int it = 0; it < 4; it++) {
        const int v4 = it * 256 + tid;
        const float4 va = rowA[v4];
        const float4 vb = rowB[v4];
        const uchar4 lb = ((const uchar4*)slab)[v4];

        const float2 a01 = a2f(va.x, va.y, ke2);
        const float2 a23 = a2f(va.z, va.w, ke2);
        const float2 b01 = a2f(vb.x, vb.y, ke2);
        const float2 b23 = a2f(vb.z, vb.w, ke2);

        float2 pa = a01; add2(pa, a23); add2(sumA2, pa);
        float2 pb = b01; add2(pb, b23); add2(sumB2, pb);

        if (lb.x == lA) { bA += ex2f(a01.x * KE); cA++; }
        if (lb.y == lA) { bA += ex2f(a01.y * KE); cA++; }
        if (lb.z == lA) { bA += ex2f(a23.x * KE); cA++; }
        if (lb.w == lA) { bA += ex2f(a23.y * KE); cA++; }

        if (lb.x == lB) { bB += ex2f(b01.x * KE); cB++; }
        if (lb.y == lB) { bB += ex2f(b01.y * KE); cB++; }
        if (lb.z == lB) { bB += ex2f(b23.x * KE); cB++; }
        if (lb.w == lB) { bB += ex2f(b23.y * KE); cB++; }
    }

    // ---- second half: d in [NN, DD): A only, both rows interleaved ----
    #pragma unroll
    for (int it = 0; it < 4; it++) {
        const int v4 = 1024 + it * 256 + tid;
        const float4 va = rowA[v4];
        const float4 vb = rowB[v4];
        const float2 a01 = a2f(va.x, va.y, ke2);
        const float2 a23 = a2f(va.z, va.w, ke2);
        const float2 b01 = a2f(vb.x, vb.y, ke2);
        const float2 b23 = a2f(vb.z, vb.w, ke2);
        float2 pa = a01; add2(pa, a23); add2(sumA2, pa);
        float2 pb = b01; add2(pb, b23); add2(sumB2, pb);
    }

    float sumA = sumA2.x + sumA2.y;
    float sumB = sumB2.x + sumB2.y;

    // ---- intra-block reduce (R4 verbatim) ----
    #pragma unroll
    for (int o = 16; o > 0; o >>= 1) {
        sumA += __shfl_down_sync(0xFFFFFFFFu, sumA, o);
        bA   += __shfl_down_sync(0xFFFFFFFFu, bA, o);
        cA   += __shfl_down_sync(0xFFFFFFFFu, cA, o);
        sumB += __shfl_down_sync(0xFFFFFFFFu, sumB, o);
        bB   += __shfl_down_sync(0xFFFFFFFFu, bB, o);
        cB   += __shfl_down_sync(0xFFFFFFFFu, cB, o);
    }
    if (lane == 0) {
        sAsum[wid] = sumA; sAB[wid] = bA; sAc[wid] = cA;
        sBsum[wid] = sumB; sBB[wid] = bB; sBc[wid] = cB;
    }
    __syncthreads();

    if (tid == 0) {
        float ts = 0.0f, tb = 0.0f;
        int   tc = 0;
        #pragma unroll
        for (int w = 0; w < 8; w++) { ts += sAsum[w]; tb += sAB[w]; tc += sAc[w]; }
        const float xd = emb[(size_t)iA * DD + iA];
        const float ad = ex2f(xd * xd * KE);       // A[i,i]
        const float dn = ts - ad;                  // denominator excludes diagonal
        tb -= ex2f(ad * KE);                       // numerator: remove diagonal term
        tc -= 1;                                   // count: remove diagonal
        s_term[0] = __logf(tb / (dn * (float)tc));
    }
    if (tid == 32) {
        float ts = 0.0f, tb = 0.0f;
        int   tc = 0;
        #pragma unroll
        for (int w = 0; w < 8; w++) { ts += sBsum[w]; tb += sBB[w]; tc += sBc[w]; }
        const float xd = emb[(size_t)iB * DD + iB];
        const float ad = ex2f(xd * xd * KE);
        const float dn = ts - ad;
        tb -= ex2f(ad * KE);
        tc -= 1;
        s_term[1] = __logf(tb / (dn * (float)tc));
    }
    __syncthreads();

    if (tid == 0) atomicAdd(out, s_term[0] + s_term[1]);
}

extern "C" void kernel_launch(void* const* d_in, const int* in_sizes, int n_in,
                              void* d_out, int out_size) {
    const float*     emb    = (const float*)d_in[0];
    const long long* labels = (const long long*)d_in[1];
    float*           out    = (float*)d_out;

    cudaMemsetAsync(out, 0, sizeof(float));
    supcon_kernel<<<NN / 2, 256>>>(emb, labels, out);
}